// round 5
// baseline (speedup 1.0000x reference)
#include <cuda_runtime.h>
#include <cuda_bf16.h>

// MatrixFactorization: out[r] = dot(concat(Wd[dow],Wt[time],Wm[month],Wdy[day]), W_item[dest])
// N=1048576, NUM_FACTOR=128, NUM_DIM=32.
//
// R4: R3 (warp-per-row loads, batched reduction, vectorized index loads) +
// occupancy recovery: __launch_bounds__(256,6) caps regs ~42 -> 48 warps/SM
// (was 32 at regs=53); 32-bit item offset math (di*128 < 2^31); data loads
// issued in 2 groups of 4 rows to keep live load-registers bounded.

#define WARPS_PER_BLOCK 8
#define THREADS (WARPS_PER_BLOCK * 32)
#define BATCH 8
#define ROWS_PER_WARP 16   // 2 batches of 8

__global__ __launch_bounds__(THREADS, 6)
void mf_kernel(const int* __restrict__ dow,
               const int* __restrict__ tim,
               const int* __restrict__ mon,
               const int* __restrict__ day,
               const int* __restrict__ dest,
               const float* __restrict__ Wdow,
               const float* __restrict__ Wtim,
               const float* __restrict__ Wmon,
               const float* __restrict__ Wday,
               const float* __restrict__ Witem,
               float* __restrict__ out,
               int n)
{
    const int warp_id = blockIdx.x * WARPS_PER_BLOCK + (threadIdx.x >> 5);
    const int lane = threadIdx.x & 31;
    const int sub = lane >> 3;        // which small table (0..3)
    const int off = (lane & 7) * 4;   // float offset within 32-dim embedding

    const float* __restrict__ Wsub =
        (sub == 0) ? Wdow : (sub == 1) ? Wtim : (sub == 2) ? Wmon : Wday;
    const int* __restrict__ idx_arr =
        (sub == 0) ? dow : (sub == 1) ? tim : (sub == 2) ? mon : day;

    // Lane that ends up holding row i of the batch after the merged tree:
    //   bit4(lane)=i bit0, bit3(lane)=i bit1, bit2(lane)=i bit2, bits0-1=0.
    const int rowid = ((lane >> 4) & 1) | (((lane >> 3) & 1) << 1) | (((lane >> 2) & 1) << 2);
    const bool is_writer = ((lane & 3) == 0);

    const int base = warp_id * ROWS_PER_WARP;
    if (base >= n) return;

#pragma unroll
    for (int b = 0; b < ROWS_PER_WARP / BATCH; b++) {
        const int rb = base + b * BATCH;

        // ---- Vectorized index loads: rb is 8-aligned -> 32B-aligned int4 ----
        int si_v[BATCH];
        int di_v[BATCH];
        {
            const int4 ia = *reinterpret_cast<const int4*>(idx_arr + rb);
            const int4 ib = *reinterpret_cast<const int4*>(idx_arr + rb + 4);
            const int4 da = *reinterpret_cast<const int4*>(dest + rb);
            const int4 db = *reinterpret_cast<const int4*>(dest + rb + 4);
            si_v[0] = ia.x; si_v[1] = ia.y; si_v[2] = ia.z; si_v[3] = ia.w;
            si_v[4] = ib.x; si_v[5] = ib.y; si_v[6] = ib.z; si_v[7] = ib.w;
            di_v[0] = da.x; di_v[1] = da.y; di_v[2] = da.z; di_v[3] = da.w;
            di_v[4] = db.x; di_v[5] = db.y; di_v[6] = db.z; di_v[7] = db.w;
        }

        float s[BATCH];

        // ---- Data loads + dot, in 2 groups of 4 rows (bounded live regs) ----
#pragma unroll
        for (int g = 0; g < 2; g++) {
            float4 u[4], v[4];
#pragma unroll
            for (int i = 0; i < 4; i++) {
                const int row = g * 4 + i;
                // 32-bit offsets: si*32 < 3.2M, di*128 < 12.8M floats.
                u[i] = *reinterpret_cast<const float4*>(Wsub + (si_v[row] * 32 + off));
                v[i] = *reinterpret_cast<const float4*>(Witem + (di_v[row] * 128 + lane * 4));
            }
#pragma unroll
            for (int i = 0; i < 4; i++) {
                float acc = u[i].x * v[i].x;
                acc = fmaf(u[i].y, v[i].y, acc);
                acc = fmaf(u[i].z, v[i].z, acc);
                acc = fmaf(u[i].w, v[i].w, acc);
                s[g * 4 + i] = acc;
            }
        }

        // ---- Merged reduction: 16 shuffles for 8 rows ----
#pragma unroll
        for (int i = 0; i < BATCH; i++)
            s[i] += __shfl_xor_sync(0xFFFFFFFFu, s[i], 16);
        float t[4];
#pragma unroll
        for (int i = 0; i < 4; i++)
            t[i] = (lane < 16) ? s[2 * i] : s[2 * i + 1];
#pragma unroll
        for (int i = 0; i < 4; i++)
            t[i] += __shfl_xor_sync(0xFFFFFFFFu, t[i], 8);
        float q[2];
#pragma unroll
        for (int i = 0; i < 2; i++)
            q[i] = ((lane & 8) == 0) ? t[2 * i] : t[2 * i + 1];
#pragma unroll
        for (int i = 0; i < 2; i++)
            q[i] += __shfl_xor_sync(0xFFFFFFFFu, q[i], 4);
        float z = ((lane & 4) == 0) ? q[0] : q[1];
        z += __shfl_xor_sync(0xFFFFFFFFu, z, 2);
        z += __shfl_xor_sync(0xFFFFFFFFu, z, 1);

        // 8 writer lanes, contiguous out[rb..rb+7] -> one 32B sector.
        if (is_writer) out[rb + rowid] = z;
    }
}

extern "C" void kernel_launch(void* const* d_in, const int* in_sizes, int n_in,
                              void* d_out, int out_size)
{
    const int*   dow   = (const int*)d_in[0];
    const int*   tim   = (const int*)d_in[1];
    const int*   mon   = (const int*)d_in[2];
    const int*   day   = (const int*)d_in[3];
    const int*   dest  = (const int*)d_in[4];
    const float* Wdow  = (const float*)d_in[5];
    const float* Wtim  = (const float*)d_in[6];
    const float* Wmon  = (const float*)d_in[7];
    const float* Wday  = (const float*)d_in[8];
    const float* Witem = (const float*)d_in[9];
    float* out = (float*)d_out;

    const int n = in_sizes[0];
    const int rows_per_block = WARPS_PER_BLOCK * ROWS_PER_WARP;  // 128
    const int grid = (n + rows_per_block - 1) / rows_per_block;

    mf_kernel<<<grid, THREADS>>>(dow, tim, mon, day, dest,
                                 Wdow, Wtim, Wmon, Wday, Witem, out, n);
}